// round 9
// baseline (speedup 1.0000x reference)
#include <cuda_runtime.h>
#include <cuda_bf16.h>
#include <math.h>

#define N0 4096
#define CH 256
#define DEG 96          // CSC bucket capacity (in-degree Poisson(32); max ~60)

#define MODE_DINV0 0
#define MODE_DINV  1
#define MODE_RELU  2

#define PADB 136

// pairs ordered so equal B-planes are adjacent (B regs loaded once per plane)
#define PAIRS_X   0x011000   // (a0,b0),(a1,b0),(a0,b1)
#define PAIRS_AGG 0x0100     // (a0,b0),(a0,b1)
#define PAIRS_AA  0x0

// ---------------- scratch (static device globals; no allocation) ----------------
static __device__ __align__(16) float g_part[2 * 4096 * 256];        // 8MB split-K partials
static __device__ __align__(16) __nv_bfloat16 g_Atb[2048 * 2048];    // 8MB transposed adjacency (bf16)
static __device__ __align__(16) __nv_bfloat16 g_Rb[1024 * 2048];     // 4MB
static __device__ __align__(16) __nv_bfloat16 g_Cbb[2048 * 1024];    // 4MB
static __device__ __align__(16) __nv_bfloat16 g_Xb[2 * N0 * CH];     // 4MB
static __device__ __align__(16) __nv_bfloat16 g_Wb[3 * 2 * CH * CH]; // 768KB
static __device__ __align__(16) __nv_bfloat16 g_xwb[2 * 2048 * CH];  // 2MB
static __device__ __align__(16) float g_fA[N0 * CH];
static __device__ __align__(16) float g_fB[N0 * CH];
static __device__ __align__(16) float g_fpart[32 * 256];
static __device__ float g_dinv[N0];
static __device__ float g_score[N0];
static __device__ int   g_perm[N0];
static __device__ int   g_csccnt[N0];
static __device__ int   g_srcs[N0 * DEG];
static __device__ int   g_cntdiag[N0];
static __device__ int   g_indeg[N0];

__device__ __forceinline__ unsigned fkey(float f) {
    unsigned u = __float_as_uint(f);
    return (u & 0x80000000u) ? ~u : (u | 0x80000000u);
}

// ---------------- graph build ----------------
__global__ void k_zero3() {
    int i = blockIdx.x * blockDim.x + threadIdx.x;
    if (i < N0) { g_csccnt[i] = 0; g_cntdiag[i] = 0; g_indeg[i] = 0; }
}

__global__ void k_fill(const int* __restrict__ ei, int E) {
    int e = blockIdx.x * blockDim.x + threadIdx.x;
    if (e >= E) return;
    int s = ei[e], d = ei[e + E];
    atomicAdd(&g_indeg[d], 1);
    if (s == d) {
        atomicAdd(&g_cntdiag[s], 1);
    } else {
        int pos = atomicAdd(&g_csccnt[d], 1);
        if (pos < DEG) g_srcs[d * DEG + pos] = s;
    }
}

// ---------------- combined split-2 of x, w0, w1, w2 ----------------
__global__ void k_splitall(const float* __restrict__ x, const float* __restrict__ w0,
                           const float* __restrict__ w1, const float* __restrict__ w2,
                           __nv_bfloat16* __restrict__ Xb, __nv_bfloat16* __restrict__ Wb) {
    const int nx = N0 * CH;
    const int nw = CH * CH;
    int idx = blockIdx.x * blockDim.x + threadIdx.x;
    float v; __nv_bfloat16 *hi, *lo;
    if (idx < nx) {
        v = x[idx];
        hi = Xb + idx; lo = Xb + nx + idx;
    } else {
        int j = idx - nx;
        if (j >= 3 * nw) return;
        int l = j >> 16, o = j & (nw - 1);
        v = (l == 0) ? w0[o] : (l == 1) ? w1[o] : w2[o];
        __nv_bfloat16* base = Wb + (size_t)l * 2 * nw;
        hi = base + o; lo = base + nw + o;
    }
    __nv_bfloat16 h = __float2bfloat16_rn(v);
    *hi = h;
    *lo = __float2bfloat16_rn(v - __bfloat162float(h));
}

// ---------------- bf16 tensor-core GEMM: ldmatrix A, vectorized B ----------------
__device__ __forceinline__ void mma16816(float* d, const unsigned* a, unsigned b0, unsigned b1) {
    asm volatile(
        "mma.sync.aligned.m16n8k16.row.col.f32.bf16.bf16.f32 "
        "{%0,%1,%2,%3}, {%4,%5,%6,%7}, {%8,%9}, {%0,%1,%2,%3};\n"
        : "+f"(d[0]), "+f"(d[1]), "+f"(d[2]), "+f"(d[3])
        : "r"(a[0]), "r"(a[1]), "r"(a[2]), "r"(a[3]), "r"(b0), "r"(b1));
}

__device__ __forceinline__ void ldsm4(unsigned* r, unsigned saddr) {
    asm volatile("ldmatrix.sync.aligned.m8n8.x4.shared.b16 {%0,%1,%2,%3}, [%4];"
                 : "=r"(r[0]), "=r"(r[1]), "=r"(r[2]), "=r"(r[3]) : "r"(saddr));
}

template <int NA, int NB>
__host__ __device__ constexpr int hgemm_smem() {
    return 2 * (NA * 128 * 40 * 2 + NB * 16 * PADB * 4);
}

template <int NA, int NB, int NPAIR, int PAIRS>
__global__ void __launch_bounds__(256, 1)
k_hgemm(const __nv_bfloat16* __restrict__ A, const __nv_bfloat16* __restrict__ B,
        float* __restrict__ Cpart, int lda, int ldb, int chunk,
        int M, int N, long aStride, long bStride) {
    extern __shared__ char sm_raw[];
    __nv_bfloat16* Asm = (__nv_bfloat16*)sm_raw;                            // [2][NA][128][40]
    unsigned* Bsm = (unsigned*)(sm_raw + 2 * NA * 128 * 40 * 2);            // [2][NB][16][PADB]

    int tid = threadIdx.x;
    int i0 = blockIdx.y * 128, j0 = blockIdx.x * 128;
    int kbeg = blockIdx.z * chunk, kend = kbeg + chunk;
    int w = tid >> 5, l = tid & 31;
    int wm = w & 3, wn = w >> 2;
    int mb = wm * 32, nb = wn * 64;
    int g = l >> 2, tg = l & 3;

    // ldmatrix lane mapping: matrix m = l>>3, row-in-matrix = l&7
    int m4 = l >> 3, ro = l & 7;
    int rowA = mb + (m4 & 1) * 8 + ro;          // + mt*16 at use
    int cofs = (m4 >> 1) * 8;                   // + ks at use
    unsigned asm_base = (unsigned)__cvta_generic_to_shared(Asm);

    float acc[2][8][4];
#pragma unroll
    for (int mt = 0; mt < 2; mt++)
#pragma unroll
        for (int j = 0; j < 8; j++)
#pragma unroll
            for (int q = 0; q < 4; q++) acc[mt][j][q] = 0.f;

    int arow = tid >> 1, apart = tid & 1;
    int bkk = tid >> 4, bnseg = tid & 15;

    auto stage = [&](int st, int k0) {
#pragma unroll
        for (int q = 0; q < NA; q++) {
            const uint4* src = (const uint4*)&A[q * aStride + (size_t)(i0 + arow) * lda + k0 + apart * 16];
            uint4* dst = (uint4*)(Asm + ((size_t)(st * NA + q) * 128 + arow) * 40 + apart * 16);
            dst[0] = src[0]; dst[1] = src[1];
        }
#pragma unroll
        for (int p = 0; p < NB; p++) {
            const __nv_bfloat16* Bp = B + p * bStride;
            uint4 lo4 = *(const uint4*)&Bp[(size_t)(k0 + 2 * bkk) * ldb + j0 + bnseg * 8];
            uint4 hi4 = *(const uint4*)&Bp[(size_t)(k0 + 2 * bkk + 1) * ldb + j0 + bnseg * 8];
            unsigned vals[8];
            vals[0] = __byte_perm(lo4.x, hi4.x, 0x5410); vals[1] = __byte_perm(lo4.x, hi4.x, 0x7632);
            vals[2] = __byte_perm(lo4.y, hi4.y, 0x5410); vals[3] = __byte_perm(lo4.y, hi4.y, 0x7632);
            vals[4] = __byte_perm(lo4.z, hi4.z, 0x5410); vals[5] = __byte_perm(lo4.z, hi4.z, 0x7632);
            vals[6] = __byte_perm(lo4.w, hi4.w, 0x5410); vals[7] = __byte_perm(lo4.w, hi4.w, 0x7632);
            // permuted layout: [kk][ (n>>6)*64 + (n&7)*8 + ((n>>3)&7) ]
            unsigned* drow = Bsm + ((size_t)(st * NB + p) * 16 + bkk) * PADB
                                 + (bnseg >> 3) * 64 + (bnseg & 7);
#pragma unroll
            for (int i = 0; i < 8; i++) drow[i * 8] = vals[i];
        }
    };

    stage(0, kbeg);
    __syncthreads();

    for (int k0 = kbeg; k0 < kend; k0 += 32) {
        int cur = ((k0 - kbeg) >> 5) & 1;
        if (k0 + 32 < kend) stage(cur ^ 1, k0 + 32);   // overlaps with compute
#pragma unroll
        for (int ks = 0; ks < 32; ks += 16) {
            unsigned a[NA][2][4];
#pragma unroll
            for (int q = 0; q < NA; q++)
#pragma unroll
                for (int mt = 0; mt < 2; mt++) {
                    unsigned sa = asm_base +
                        ((unsigned)((cur * NA + q) * 128 + rowA + mt * 16) * 40 + ks + cofs) * 2;
                    ldsm4(a[q][mt], sa);
                }
            int kk0 = (ks >> 1) + tg;
            unsigned bb0[8], bb1[8];
#pragma unroll
            for (int p = 0; p < NPAIR; p++) {
                const int ai = (PAIRS >> (8 * p + 4)) & 0xF;
                const int bi = (PAIRS >> (8 * p)) & 0xF;
                const int prev_bi = p ? ((PAIRS >> (8 * (p - 1))) & 0xF) : -1;
                if (bi != prev_bi) {
                    const unsigned* Bq = Bsm + (size_t)(cur * NB + bi) * 16 * PADB;
                    const unsigned* r0p = Bq + kk0 * PADB + nb + g * 8;
                    const unsigned* r1p = Bq + (kk0 + 4) * PADB + nb + g * 8;
                    *(uint4*)&bb0[0] = *(const uint4*)r0p;
                    *(uint4*)&bb0[4] = *(const uint4*)(r0p + 4);
                    *(uint4*)&bb1[0] = *(const uint4*)r1p;
                    *(uint4*)&bb1[4] = *(const uint4*)(r1p + 4);
                }
#pragma unroll
                for (int j = 0; j < 8; j++) {
                    mma16816(acc[0][j], a[ai][0], bb0[j], bb1[j]);
                    mma16816(acc[1][j], a[ai][1], bb0[j], bb1[j]);
                }
            }
        }
        __syncthreads();
    }
    float* Cp = Cpart + (size_t)blockIdx.z * M * N;
#pragma unroll
    for (int mt = 0; mt < 2; mt++) {
        int gr = i0 + mb + mt * 16 + g;
#pragma unroll
        for (int j = 0; j < 8; j++) {
            int gc = j0 + nb + j * 8 + tg * 2;
            *(float2*)&Cp[(size_t)gr * N + gc] = make_float2(acc[mt][j][0], acc[mt][j][1]);
            *(float2*)&Cp[(size_t)(gr + 8) * N + gc] = make_float2(acc[mt][j][2], acc[mt][j][3]);
        }
    }
}

// ---------------- split-K reduce, one block per output row (N=256) ----------------
__global__ void k_reduceF(const float* __restrict__ Cpart, float* __restrict__ out,
                          int SK, int M, int mode, const float* __restrict__ bias,
                          const float* __restrict__ p) {
    __shared__ float red[256], red2[256];
    int row = blockIdx.x, t = threadIdx.x;
    int idx = row * 256 + t;
    float s = 0.f;
    for (int z = 0; z < SK; z++) s += Cpart[(size_t)z * M * 256 + idx];
    float v;
    if (mode == MODE_DINV0) {
        float deg = (float)g_indeg[row] + ((g_cntdiag[row] == 0) ? 2.0f : 0.0f);
        v = s * rsqrtf(deg);
    } else if (mode == MODE_DINV) {
        v = s * g_dinv[row];
    } else {
        v = fmaxf(g_dinv[row] * s + bias[t], 0.f);
    }
    out[idx] = v;
    if (p != nullptr) {
        float pv = p[t];
        red[t] = v * pv; red2[t] = pv * pv;
        __syncthreads();
        for (int off = 128; off > 0; off >>= 1) {
            if (t < off) { red[t] += red[t + off]; red2[t] += red2[t + off]; }
            __syncthreads();
        }
        if (t == 0) g_score[row] = tanhf(red[0] * rsqrtf(red2[0]));
    }
}

// split-K reduce -> dinv scale -> split-2 bf16 planes
__global__ void k_reduce_ds2(const float* __restrict__ Cpart, __nv_bfloat16* __restrict__ out,
                             int SK, int M, int N) {
    int idx = blockIdx.x * blockDim.x + threadIdx.x;
    if (idx >= M * N) return;
    float s = 0.f;
    for (int z = 0; z < SK; z++) s += Cpart[(size_t)z * M * N + idx];
    float v = s * g_dinv[idx / N];
    __nv_bfloat16 h = __float2bfloat16_rn(v);
    out[idx] = h;
    out[(size_t)M * N + idx] = __float2bfloat16_rn(v - __bfloat162float(h));
}

// split-K reduce for A2^T, one block per row: diag->2, bf16 out, exact rowsum -> g_dinv
__global__ void k_reduce_A2t(const float* __restrict__ Cpart, __nv_bfloat16* __restrict__ out,
                             int n) {
    __shared__ float red[256];
    int row = blockIdx.x, t = threadIdx.x;
    float part = 0.f;
    for (int c = t; c < n; c += 256) {
        size_t idx = (size_t)row * n + c;
        float s = Cpart[idx] + Cpart[(size_t)n * n + idx];
        float v = (row == c) ? 2.0f : s;
        out[idx] = __float2bfloat16_rn(v);
        part += v;
    }
    red[t] = part; __syncthreads();
    for (int off = 128; off > 0; off >>= 1) { if (t < off) red[t] += red[t + off]; __syncthreads(); }
    if (t == 0) g_dinv[row] = rsqrtf(red[0]);
}

// ---------------- level-0 GCN aggregation (bucketed CSC) + fused score ----------------
__global__ void k_agg0(const float* __restrict__ B, const float* __restrict__ bias,
                       float* __restrict__ out, const float* __restrict__ p) {
    __shared__ float red[256], red2[256];
    int d = blockIdx.x, t = threadIdx.x;
    int cd = g_cntdiag[d];
    float w0 = (cd == 0) ? 2.0f : (float)cd;
    float acc = w0 * B[(size_t)d * CH + t];
    int cnt = g_csccnt[d];
    const int* src = &g_srcs[d * DEG];
#pragma unroll 4
    for (int e = 0; e < cnt; e++) {
        int s = __ldg(&src[e]);
        acc += B[(size_t)s * CH + t];
    }
    float deg = (float)g_indeg[d] + ((cd == 0) ? 2.0f : 0.0f);
    float v = fmaxf(rsqrtf(deg) * acc + bias[t], 0.0f);
    out[(size_t)d * CH + t] = v;
    float pv = p[t];
    red[t] = v * pv; red2[t] = pv * pv;
    __syncthreads();
    for (int off = 128; off > 0; off >>= 1) {
        if (t < off) { red[t] += red[t + off]; red2[t] += red2[t + off]; }
        __syncthreads();
    }
    if (t == 0) g_score[d] = tanhf(red[0] * rsqrtf(red2[0]));
}

// ---------------- level-1 augment in TRANSPOSED space via CSC ----------------
__global__ void k_augmentT(__nv_bfloat16* __restrict__ Atb) {
    __shared__ float s[N0];
    __shared__ int sp[2048];
    __shared__ float red[256];
    int r = blockIdx.x, t = threadIdx.x;
    for (int c = t; c < N0; c += 256) s[c] = 0.f;
    for (int c = t; c < 2048; c += 256) sp[c] = g_perm[c];
    __syncthreads();
    int i = sp[r];
    int lane = t & 31, w = t >> 5;
    int cnt = g_csccnt[i];
    const int* isrc = &g_srcs[i * DEG];
    for (int e = w; e < cnt; e += 8) {
        int kc = isrc[e];
        if (lane == 0) atomicAdd(&s[kc], 2.0f);
        int cnt2 = g_csccnt[kc];
        const int* ksrc = &g_srcs[kc * DEG];
        for (int f = lane; f < cnt2; f += 32) atomicAdd(&s[ksrc[f]], 1.0f);
    }
    __syncthreads();
    __nv_bfloat16* row = Atb + (size_t)r * 2048;
    float part = 0.f;
    for (int c = t; c < 2048; c += 256) {
        float v = (c == r) ? 2.0f : s[sp[c]];
        row[c] = __float2bfloat16_rn(v);
        part += v;
    }
    red[t] = part; __syncthreads();
    for (int off = 128; off > 0; off >>= 1) { if (t < off) red[t] += red[t + off]; __syncthreads(); }
    if (t == 0) g_dinv[r] = rsqrtf(red[0]);
}

// ---------------- top-k threshold + collect (fused, single block) ----------------
__global__ void k_threshcollect(int n, int k) {
    __shared__ unsigned u[N0];
    __shared__ int sc[2];
    int t = threadIdx.x;
    int per = n >> 10;
    for (int i = t; i < n; i += 1024) u[i] = fkey(g_score[i]);
    __syncthreads();
    unsigned thr = 0;
    for (int bit = 31; bit >= 0; --bit) {
        unsigned cand = thr | (1u << bit);
        int c = 0;
        for (int j = 0; j < per; j++)
            c += __syncthreads_count(u[j * 1024 + t] >= cand);
        if (c >= k) thr = cand;
    }
    int cg = 0;
    for (int j = 0; j < per; j++)
        cg += __syncthreads_count(u[j * 1024 + t] > thr);
    if (t == 0) { sc[0] = 0; sc[1] = 0; }
    __syncthreads();
    for (int i = t; i < n; i += 1024) {
        unsigned v = u[i];
        if (v > thr) {
            int p = atomicAdd(&sc[0], 1);
            g_perm[p] = i;
        } else if (v == thr) {
            int p = atomicAdd(&sc[1], 1);
            int pos = cg + p;
            if (pos < k) g_perm[pos] = i;
        }
    }
}

// gather + gate + split-2 bf16
__global__ void k_gather_xb(const float* __restrict__ src, __nv_bfloat16* __restrict__ dst, int k) {
    int idx = blockIdx.x * blockDim.x + threadIdx.x;
    if (idx >= k * CH) return;
    int r = idx >> 8;
    int p = g_perm[r];
    float v = src[(size_t)p * CH + (idx & 255)] * g_score[p];
    __nv_bfloat16 h = __float2bfloat16_rn(v);
    dst[idx] = h;
    dst[(size_t)k * CH + idx] = __float2bfloat16_rn(v - __bfloat162float(h));
}

// fused level-2 gathers (R and C halves in one launch)
__global__ void k_gather_RC(const __nv_bfloat16* __restrict__ At,
                            __nv_bfloat16* __restrict__ R, __nv_bfloat16* __restrict__ Cb,
                            int kold, int kn) {
    int idx = blockIdx.x * blockDim.x + threadIdx.x;
    int tot = kn * kold;
    if (idx < tot) {
        int r = idx / kold, k = idx - r * kold;
        int p = g_perm[r];
        R[idx] = (k == p) ? __float2bfloat16_rn(1.0f) : At[(size_t)p * kold + k];
    } else if (idx < 2 * tot) {
        int j = idx - tot;
        int k = j / kn, c = j - k * kn;
        int p = g_perm[c];
        Cb[j] = (k == p) ? __float2bfloat16_rn(1.0f) : At[(size_t)k * kold + p];
    }
}

// ---------------- final readout ----------------
__global__ void k_rowsum_f(const float* __restrict__ F, int n) {
    int t = threadIdx.x;
    int rows = n / 32;
    float s = 0.f;
    int r0 = blockIdx.x * rows;
    for (int r = r0; r < r0 + rows; r++) s += F[(size_t)r * CH + t];
    g_fpart[blockIdx.x * 256 + t] = s;
}

__global__ void k_final(int n, const float* __restrict__ wc,
                        const float* __restrict__ bc, float* __restrict__ out, int out_size) {
    __shared__ float red[256];
    __shared__ float lg[16];
    int t = threadIdx.x;
    float s = 0.f;
#pragma unroll
    for (int b = 0; b < 32; b++) s += g_fpart[b * 256 + t];
    float mv = s / (float)n;
    red[t] = mv * mv; __syncthreads();
    for (int off = 128; off > 0; off >>= 1) { if (t < off) red[t] += red[t + off]; __syncthreads(); }
    float nrm = fmaxf(sqrtf(red[0]), 1e-12f);
    __syncthreads();
    float e = mv / nrm;
    for (int j = 0; j < 10; j++) {
        red[t] = e * wc[j * CH + t]; __syncthreads();
        for (int off = 128; off > 0; off >>= 1) { if (t < off) red[t] += red[t + off]; __syncthreads(); }
        if (t == 0) lg[j] = red[0] + bc[j];
        __syncthreads();
    }
    if (t == 0) {
        float mx = lg[0];
        for (int j = 1; j < 10; j++) mx = fmaxf(mx, lg[j]);
        float se = 0.f;
        for (int j = 0; j < 10; j++) se += expf(lg[j] - mx);
        float lse = logf(se) + mx;
        for (int j = 0; j < 10; j++) lg[j] -= lse;
    }
    __syncthreads();
    if (t < out_size && t < CH) out[t] = e;
    if (t < 10 && CH + t < out_size) out[CH + t] = lg[t];
    for (int idx = 266 + t; idx < out_size; idx += 256) out[idx] = 0.0f;
}

// ---------------- launch ----------------
extern "C" void kernel_launch(void* const* d_in, const int* in_sizes, int n_in,
                              void* d_out, int out_size) {
    const float* x  = (const float*)d_in[0];
    const int*   ei = (const int*)d_in[1];
    const float* w0 = (const float*)d_in[2];
    const float* b0 = (const float*)d_in[3];
    const float* w1 = (const float*)d_in[4];
    const float* b1 = (const float*)d_in[5];
    const float* w2 = (const float*)d_in[6];
    const float* b2 = (const float*)d_in[7];
    const float* p1 = (const float*)d_in[8];
    const float* p2 = (const float*)d_in[9];
    const float* wc = (const float*)d_in[10];
    const float* bc = (const float*)d_in[11];
    float* out = (float*)d_out;
    int E = in_sizes[1] / 2;
    const int n0 = N0, k1 = 2048, k2 = 1024;
    const int NW = CH * CH;

    float *pPart, *pfA, *pfB;
    __nv_bfloat16 *pAtb, *pRb, *pCbb, *pXb, *pWb, *pXwb;
    cudaGetSymbolAddress((void**)&pPart, g_part);
    cudaGetSymbolAddress((void**)&pfA, g_fA);
    cudaGetSymbolAddress((void**)&pfB, g_fB);
    cudaGetSymbolAddress((void**)&pAtb, g_Atb);
    cudaGetSymbolAddress((void**)&pRb,  g_Rb);
    cudaGetSymbolAddress((void**)&pCbb, g_Cbb);
    cudaGetSymbolAddress((void**)&pXb,  g_Xb);
    cudaGetSymbolAddress((void**)&pWb,  g_Wb);
    cudaGetSymbolAddress((void**)&pXwb, g_xwb);

    constexpr int SM22 = hgemm_smem<2, 2>();
    constexpr int SM12 = hgemm_smem<1, 2>();
    constexpr int SM11 = hgemm_smem<1, 1>();
    cudaFuncSetAttribute(k_hgemm<2, 2, 3, PAIRS_X>,
                         cudaFuncAttributeMaxDynamicSharedMemorySize, SM22);
    cudaFuncSetAttribute(k_hgemm<1, 2, 2, PAIRS_AGG>,
                         cudaFuncAttributeMaxDynamicSharedMemorySize, SM12);
    cudaFuncSetAttribute(k_hgemm<1, 1, 1, PAIRS_AA>,
                         cudaFuncAttributeMaxDynamicSharedMemorySize, SM11);

    // ---- graph build + all conversions up front ----
    k_zero3<<<(N0 + 255) / 256, 256>>>();
    k_splitall<<<(n0 * CH + 3 * NW + 255) / 256, 256>>>(x, w0, w1, w2, pXb, pWb);
    k_fill<<<(E + 255) / 256, 256>>>(ei, E);

    // ---- GCN level 0 ----
    k_hgemm<2, 2, 3, PAIRS_X><<<dim3(2, 32, 2), 256, SM22>>>(pXb, pWb, pPart, 256, 256, 128,
                                                              n0, 256, (long)n0 * CH, (long)NW);
    k_reduceF<<<n0, 256>>>(pPart, pfB, 2, n0, MODE_DINV0, nullptr, nullptr);
    k_agg0<<<n0, 256>>>(pfB, b0, pfA, p1);                      // F0 + score1

    // ---- pool 1 ----
    k_threshcollect<<<1, 1024>>>(n0, k1);
    k_gather_xb<<<(k1 * CH + 255) / 256, 256>>>(pfA, pXb, k1);  // X1 split-2

    // ---- augment level 1 ----
    k_augmentT<<<k1, 256>>>(pAtb);

    // ---- GCN level 1 ----
    k_hgemm<2, 2, 3, PAIRS_X><<<dim3(2, 16, 4), 256, SM22>>>(pXb, pWb + 2 * NW, pPart, 256, 256, 64,
                                                              k1, 256, (long)k1 * CH, (long)NW);
    k_reduce_ds2<<<(k1 * 256 + 255) / 256, 256>>>(pPart, pXwb, 4, k1, 256);
    k_hgemm<1, 2, 2, PAIRS_AGG><<<dim3(2, 16, 4), 256, SM12>>>(pAtb, pXwb, pPart, k1, 256, 512,
                                                                k1, 256, 0, (long)k1 * CH);
    k_reduceF<<<k1, 256>>>(pPart, pfA, 4, k1, MODE_RELU, b1, p2);  // F1 + score2

    // ---- pool 2 ----
    k_threshcollect<<<1, 1024>>>(k1, k2);
    k_gather_xb<<<(k2 * CH + 255) / 256, 256>>>(pfA, pXb, k2);  // X2 split-2

    // ---- augment level 2 ----
    k_gather_RC<<<(2 * k2 * k1 + 255) / 256, 256>>>(pAtb, pRb, pCbb, k1, k2);
    k_hgemm<1, 1, 1, PAIRS_AA><<<dim3(8, 8, 2), 256, SM11>>>(pRb, pCbb, pPart, k1, k2, 1024,
                                                              k2, k2, 0, 0);
    k_reduce_A2t<<<k2, 256>>>(pPart, pAtb, k2);                 // Atb=A2t + dinv

    // ---- GCN level 2 ----
    k_hgemm<2, 2, 3, PAIRS_X><<<dim3(2, 8, 8), 256, SM22>>>(pXb, pWb + 4 * NW, pPart, 256, 256, 32,
                                                             k2, 256, (long)k2 * CH, (long)NW);
    k_reduce_ds2<<<(k2 * 256 + 255) / 256, 256>>>(pPart, pXwb, 8, k2, 256);
    k_hgemm<1, 2, 2, PAIRS_AGG><<<dim3(2, 8, 8), 256, SM12>>>(pAtb, pXwb, pPart, k2, 256, 128,
                                                               k2, 256, 0, (long)k2 * CH);
    k_reduceF<<<k2, 256>>>(pPart, pfA, 8, k2, MODE_RELU, b2, nullptr);  // F2

    // ---- readout ----
    k_rowsum_f<<<32, 256>>>(pfA, k2);
    k_final<<<1, 256>>>(k2, wc, bc, out, out_size);
}